// round 14
// baseline (speedup 1.0000x reference)
#include <cuda_runtime.h>
#include <math_constants.h>

#define NBINS 512
#define KNN   16
#define BATCH 8192
#define NROWS 100000

// Scratch (__device__ globals: allocation-free rule). Zero-initialized at
// module load; final_kernel re-zeros everything after use, so the "== 0 on
// entry" invariant holds for every call (graph replays included).
__device__ __align__(16) float g_bcol[NBINS];  // atomic column sums
__device__ double g_sum;                       // atomic sum of add*weight

// One uniform launch: block b loads base row b (needed for the gather anyway)
// and folds it into g_bcol via atomics (8192 adds/column over ~35us is ~10x
// under the LTS per-address serialize limit -> fully hidden). Then warp w
// computes add[b,w] = max_j (outputs[nns[b,w], j] + base[j]).
__global__ __launch_bounds__(512, 4)
void fused_kernel(const float* __restrict__ outputs,
                  const float* __restrict__ y,
                  const float* __restrict__ weights,
                  float* __restrict__ booster) {
    __shared__ __align__(16) float base[NBINS];
    __shared__ float s_add[KNN];

    int b    = blockIdx.x;
    int tid  = threadIdx.x;
    int warp = tid >> 5;
    int lane = tid & 31;

    float v = outputs[(size_t)b * NBINS + tid];
    base[tid] = v;
    atomicAdd(&g_bcol[tid], v);        // colsum contribution (RED, hidden)
    __syncthreads();

    int idx = (int)y[b * KNN + warp];   // trunc; y >= 0
    const float4* g4 = (const float4*)(outputs + (size_t)idx * NBINS);
    const float4* b4 = (const float4*)base;

    float m = -CUDART_INF_F;
#pragma unroll
    for (int t = 0; t < 4; t++) {
        float4 a = g4[t * 32 + lane];
        float4 c = b4[t * 32 + lane];
        m = fmaxf(m, fmaxf(fmaxf(a.x + c.x, a.y + c.y),
                           fmaxf(a.z + c.z, a.w + c.w)));
    }
#pragma unroll
    for (int o = 16; o; o >>= 1)
        m = fmaxf(m, __shfl_xor_sync(0xFFFFFFFFu, m, o));
    if (lane == 0) s_add[warp] = m;
    __syncthreads();

    if (tid == 0) {
        float s = 0.0f;
#pragma unroll
        for (int k = 0; k < KNN; k++) s += s_add[k];
        booster[b] = fmaxf(0.5f, (2.0f - s * (1.0f / KNN)) * 0.5f);
        atomicAdd(&g_sum, (double)(s * weights[b]));
    }

    // Let the PDL-launched final_kernel spin up as our last wave drains.
    cudaTriggerProgrammaticLaunchCompletion();
}

// Lean final (PDL secondary): 128 threads, reads 2KB (one float4 each),
// zero-restores it, min/max reduce, one scalar read.
__global__ void final_kernel(float* __restrict__ out) {
    __shared__ float smx[4], smn[4];
    int t    = threadIdx.x;       // 0..127
    int warp = t >> 5;
    int lane = t & 31;

    cudaGridDependencySynchronize();

    float4* p4 = (float4*)&g_bcol[0];
    float4 v = p4[t];
    p4[t] = make_float4(0.f, 0.f, 0.f, 0.f);   // restore invariant

    float mx = fmaxf(fmaxf(v.x, v.y), fmaxf(v.z, v.w));
    float mn = fminf(fminf(v.x, v.y), fminf(v.z, v.w));
#pragma unroll
    for (int o = 16; o; o >>= 1) {
        mx = fmaxf(mx, __shfl_xor_sync(0xFFFFFFFFu, mx, o));
        mn = fminf(mn, __shfl_xor_sync(0xFFFFFFFFu, mn, o));
    }
    if (lane == 0) { smx[warp] = mx; smn[warp] = mn; }
    __syncthreads();

    if (t == 0) {
        mx = fmaxf(fmaxf(smx[0], smx[1]), fmaxf(smx[2], smx[3]));
        mn = fminf(fminf(smn[0], smn[1]), fminf(smn[2], smn[3]));
        double ds = g_sum;
        g_sum = 0.0;                           // restore invariant

        float bb       = mx - mn;
        float target_b = (float)NROWS / (float)NBINS;
        float ratio    = bb / target_b;
        float add_mean = (float)(ds / (double)(BATCH * KNN));
        float d        = 2.0f - add_mean;
        d = d * d;
        out[0] = ratio + d;  // cost
        out[1] = d;          // diff
        out[2] = ratio;      // b / target_b
    }
}

extern "C" void kernel_launch(void* const* d_in, const int* in_sizes, int n_in,
                              void* d_out, int out_size) {
    const float* outputs = (const float*)d_in[0];
    const float* y       = (const float*)d_in[1];
    const float* weights = (const float*)d_in[2];
    float* out = (float*)d_out;

    fused_kernel<<<BATCH, NBINS>>>(outputs, y, weights, out + 3);

    // PDL launch of the epilogue: overlaps its launch latency with fused.
    cudaLaunchConfig_t cfg = {};
    cfg.gridDim  = dim3(1, 1, 1);
    cfg.blockDim = dim3(128, 1, 1);
    cfg.stream   = 0;
    cudaLaunchAttribute attr[1];
    attr[0].id = cudaLaunchAttributeProgrammaticStreamSerialization;
    attr[0].val.programmaticStreamSerializationAllowed = 1;
    cfg.attrs    = attr;
    cfg.numAttrs = 1;
    cudaLaunchKernelEx(&cfg, final_kernel, out);
}

// round 15
// speedup vs baseline: 2.0961x; 2.0961x over previous
#include <cuda_runtime.h>
#include <math_constants.h>

#define NBINS 512
#define KNN   16
#define BATCH 8192
#define NROWS 100000
#define SLOTS 8           // column-sum accumulator slots (b & 7); burst-safe

// Scratch (__device__ globals: allocation-free rule). Zero-initialized at
// module load; final_kernel re-zeros everything after use, so the "== 0 on
// entry" invariant holds for every call (graph replays included).
__device__ __align__(16) float g_part[SLOTS][NBINS];  // sliced atomic column sums
__device__ double g_sum;                              // atomic sum of add*weight

// One uniform launch: block b loads base row b (needed for the gather anyway)
// and folds it into the column sums via sliced atomics (burst contention ~18
// per address per wave -> hidden). Then warp w computes
// add[b,w] = max_j (outputs[nns[b,w], j] + base[j]).
__global__ __launch_bounds__(512, 4)
void fused_kernel(const float* __restrict__ outputs,
                  const float* __restrict__ y,
                  const float* __restrict__ weights,
                  float* __restrict__ booster) {
    __shared__ __align__(16) float base[NBINS];
    __shared__ float s_add[KNN];
    __shared__ int   s_idx[KNN];

    int b    = blockIdx.x;
    int tid  = threadIdx.x;
    int warp = tid >> 5;
    int lane = tid & 31;

    // Warp 0: one coalesced load of all 16 neighbor indices -> SMEM.
    if (warp == 0 && lane < KNN)
        s_idx[lane] = (int)y[b * KNN + lane];   // trunc; y >= 0

    float v = outputs[(size_t)b * NBINS + tid];
    base[tid] = v;
    atomicAdd(&g_part[b & (SLOTS - 1)][tid], v);   // colsum contribution (RED)
    __syncthreads();

    int idx = s_idx[warp];
    const float4* g4 = (const float4*)(outputs + (size_t)idx * NBINS);
    const float4* b4 = (const float4*)base;

    float m = -CUDART_INF_F;
#pragma unroll
    for (int t = 0; t < 4; t++) {
        float4 a = g4[t * 32 + lane];
        float4 c = b4[t * 32 + lane];
        m = fmaxf(m, fmaxf(fmaxf(a.x + c.x, a.y + c.y),
                           fmaxf(a.z + c.z, a.w + c.w)));
    }
#pragma unroll
    for (int o = 16; o; o >>= 1)
        m = fmaxf(m, __shfl_xor_sync(0xFFFFFFFFu, m, o));
    if (lane == 0) s_add[warp] = m;
    __syncthreads();

    if (tid == 0) {
        float s = 0.0f;
#pragma unroll
        for (int k = 0; k < KNN; k++) s += s_add[k];
        booster[b] = fmaxf(0.5f, (2.0f - s * (1.0f / KNN)) * 0.5f);
        atomicAdd(&g_sum, (double)(s * weights[b]));
    }

    // Let the PDL-launched final_kernel spin up as our last wave drains.
    cudaTriggerProgrammaticLaunchCompletion();
}

// Lean final (PDL secondary): 128 threads, float4 traffic only.
// Thread t owns columns 4t..4t+3. Reads 16KB, zero-restores it, min/max
// reduce, one scalar read. Restores all zero-invariants.
__global__ void final_kernel(float* __restrict__ out) {
    __shared__ float smx[4], smn[4];
    int t    = threadIdx.x;       // 0..127
    int warp = t >> 5;
    int lane = t & 31;

    cudaGridDependencySynchronize();

    float4* p4 = (float4*)&g_part[0][0];
    const float4 z4 = make_float4(0.f, 0.f, 0.f, 0.f);

    float4 v = z4;
#pragma unroll
    for (int s = 0; s < SLOTS; s++) {
        float4 a = p4[s * (NBINS / 4) + t];
        v.x += a.x; v.y += a.y; v.z += a.z; v.w += a.w;
        p4[s * (NBINS / 4) + t] = z4;      // restore invariant
    }
    float mx = fmaxf(fmaxf(v.x, v.y), fmaxf(v.z, v.w));
    float mn = fminf(fminf(v.x, v.y), fminf(v.z, v.w));
#pragma unroll
    for (int o = 16; o; o >>= 1) {
        mx = fmaxf(mx, __shfl_xor_sync(0xFFFFFFFFu, mx, o));
        mn = fminf(mn, __shfl_xor_sync(0xFFFFFFFFu, mn, o));
    }
    if (lane == 0) { smx[warp] = mx; smn[warp] = mn; }
    __syncthreads();

    if (t == 0) {
        mx = fmaxf(fmaxf(smx[0], smx[1]), fmaxf(smx[2], smx[3]));
        mn = fminf(fminf(smn[0], smn[1]), fminf(smn[2], smn[3]));
        double ds = g_sum;
        g_sum = 0.0;                       // restore invariant

        float bb       = mx - mn;
        float target_b = (float)NROWS / (float)NBINS;
        float ratio    = bb / target_b;
        float add_mean = (float)(ds / (double)(BATCH * KNN));
        float d        = 2.0f - add_mean;
        d = d * d;
        out[0] = ratio + d;  // cost
        out[1] = d;          // diff
        out[2] = ratio;      // b / target_b
    }
}

extern "C" void kernel_launch(void* const* d_in, const int* in_sizes, int n_in,
                              void* d_out, int out_size) {
    const float* outputs = (const float*)d_in[0];
    const float* y       = (const float*)d_in[1];
    const float* weights = (const float*)d_in[2];
    float* out = (float*)d_out;

    fused_kernel<<<BATCH, NBINS>>>(outputs, y, weights, out + 3);

    // PDL launch of the epilogue: overlaps its launch latency with fused.
    cudaLaunchConfig_t cfg = {};
    cfg.gridDim  = dim3(1, 1, 1);
    cfg.blockDim = dim3(128, 1, 1);
    cfg.stream   = 0;
    cudaLaunchAttribute attr[1];
    attr[0].id = cudaLaunchAttributeProgrammaticStreamSerialization;
    attr[0].val.programmaticStreamSerializationAllowed = 1;
    cfg.attrs    = attr;
    cfg.numAttrs = 1;
    cudaLaunchKernelEx(&cfg, final_kernel, out);
}

// round 16
// speedup vs baseline: 2.1966x; 1.0479x over previous
#include <cuda_runtime.h>
#include <math_constants.h>

#define NBINS 512
#define KNN   16
#define BATCH 8192
#define NROWS 100000
#define SLOTS 8           // column-sum accumulator slots (b & 7); burst-safe

// Scratch (__device__ globals: allocation-free rule). Zero-initialized at
// module load; final_kernel re-zeros everything after use, so the "== 0 on
// entry" invariant holds for every call (graph replays included).
__device__ __align__(16) float g_part[SLOTS][NBINS];  // sliced atomic column sums
__device__ double g_sum;                              // atomic sum of add*weight

// One uniform launch: block b loads base row b, computes
// add[b,w] = max_j (outputs[nns[b,w], j] + base[j]) per warp w, and folds the
// base row into the sliced column sums AFTER the gather loop so the RED burst
// never gates block startup.
__global__ __launch_bounds__(512, 4)
void fused_kernel(const float* __restrict__ outputs,
                  const float* __restrict__ y,
                  const float* __restrict__ weights,
                  float* __restrict__ booster) {
    __shared__ __align__(16) float base[NBINS];
    __shared__ float s_add[KNN];

    int b    = blockIdx.x;
    int tid  = threadIdx.x;
    int warp = tid >> 5;
    int lane = tid & 31;

    float v = outputs[(size_t)b * NBINS + tid];
    base[tid] = v;
    __syncthreads();

    int idx = (int)y[b * KNN + warp];   // trunc; y >= 0
    const float4* g4 = (const float4*)(outputs + (size_t)idx * NBINS);
    const float4* b4 = (const float4*)base;

    float m = -CUDART_INF_F;
#pragma unroll
    for (int t = 0; t < 4; t++) {
        float4 a = g4[t * 32 + lane];
        float4 c = b4[t * 32 + lane];
        m = fmaxf(m, fmaxf(fmaxf(a.x + c.x, a.y + c.y),
                           fmaxf(a.z + c.z, a.w + c.w)));
    }

    // Colsum contribution in the drain phase (v still in register).
    atomicAdd(&g_part[b & (SLOTS - 1)][tid], v);

#pragma unroll
    for (int o = 16; o; o >>= 1)
        m = fmaxf(m, __shfl_xor_sync(0xFFFFFFFFu, m, o));
    if (lane == 0) s_add[warp] = m;
    __syncthreads();

    if (tid == 0) {
        float s = 0.0f;
#pragma unroll
        for (int k = 0; k < KNN; k++) s += s_add[k];
        booster[b] = fmaxf(0.5f, (2.0f - s * (1.0f / KNN)) * 0.5f);
        atomicAdd(&g_sum, (double)(s * weights[b]));
    }

    // Let the PDL-launched final_kernel spin up as our last wave drains.
    cudaTriggerProgrammaticLaunchCompletion();
}

// Lean final (PDL secondary): 128 threads, float4 traffic only.
// Thread t owns columns 4t..4t+3. Reads 16KB, zero-restores it, min/max
// reduce, one scalar read. Restores all zero-invariants.
__global__ void final_kernel(float* __restrict__ out) {
    __shared__ float smx[4], smn[4];
    int t    = threadIdx.x;       // 0..127
    int warp = t >> 5;
    int lane = t & 31;

    cudaGridDependencySynchronize();

    float4* p4 = (float4*)&g_part[0][0];
    const float4 z4 = make_float4(0.f, 0.f, 0.f, 0.f);

    float4 v = z4;
#pragma unroll
    for (int s = 0; s < SLOTS; s++) {
        float4 a = p4[s * (NBINS / 4) + t];
        v.x += a.x; v.y += a.y; v.z += a.z; v.w += a.w;
        p4[s * (NBINS / 4) + t] = z4;      // restore invariant
    }
    float mx = fmaxf(fmaxf(v.x, v.y), fmaxf(v.z, v.w));
    float mn = fminf(fminf(v.x, v.y), fminf(v.z, v.w));
#pragma unroll
    for (int o = 16; o; o >>= 1) {
        mx = fmaxf(mx, __shfl_xor_sync(0xFFFFFFFFu, mx, o));
        mn = fminf(mn, __shfl_xor_sync(0xFFFFFFFFu, mn, o));
    }
    if (lane == 0) { smx[warp] = mx; smn[warp] = mn; }
    __syncthreads();

    if (t == 0) {
        mx = fmaxf(fmaxf(smx[0], smx[1]), fmaxf(smx[2], smx[3]));
        mn = fminf(fminf(smn[0], smn[1]), fminf(smn[2], smn[3]));
        double ds = g_sum;
        g_sum = 0.0;                       // restore invariant

        float bb       = mx - mn;
        float target_b = (float)NROWS / (float)NBINS;
        float ratio    = bb / target_b;
        float add_mean = (float)(ds / (double)(BATCH * KNN));
        float d        = 2.0f - add_mean;
        d = d * d;
        out[0] = ratio + d;  // cost
        out[1] = d;          // diff
        out[2] = ratio;      // b / target_b
    }
}

extern "C" void kernel_launch(void* const* d_in, const int* in_sizes, int n_in,
                              void* d_out, int out_size) {
    const float* outputs = (const float*)d_in[0];
    const float* y       = (const float*)d_in[1];
    const float* weights = (const float*)d_in[2];
    float* out = (float*)d_out;

    fused_kernel<<<BATCH, NBINS>>>(outputs, y, weights, out + 3);

    // PDL launch of the epilogue: overlaps its launch latency with fused.
    cudaLaunchConfig_t cfg = {};
    cfg.gridDim  = dim3(1, 1, 1);
    cfg.blockDim = dim3(128, 1, 1);
    cfg.stream   = 0;
    cudaLaunchAttribute attr[1];
    attr[0].id = cudaLaunchAttributeProgrammaticStreamSerialization;
    attr[0].val.programmaticStreamSerializationAllowed = 1;
    cfg.attrs    = attr;
    cfg.numAttrs = 1;
    cudaLaunchKernelEx(&cfg, final_kernel, out);
}